// round 16
// baseline (speedup 1.0000x reference)
#include <cuda_runtime.h>
#include <cstdint>

// ---------------- problem constants (shapes fixed by the dataset) ----------
#define NMAX   50000
#define EMAX   800000
#define HDIM   128
#define CDIM   256      // 2*H
#define GNUM   128

// ---------------- scratch (static device globals; no runtime allocation) --
__device__ __align__(16) float g_h     [NMAX * HDIM];
__device__ __align__(16) float g_zA    [NMAX * CDIM];
__device__ __align__(16) float g_zB    [NMAX * CDIM];
__device__ __align__(16) float g_out   [NMAX * HDIM];
__device__ __align__(16) float g_W1f   [92 * 384];        // fused [W1 | embed_w]
__device__ __align__(16) float g_b1f   [384];
__device__ __align__(16) float g_W2    [40 * CDIM];
__device__ __align__(16) float g_b2    [CDIM];
__device__ __align__(16) float g_S     [NMAX * 48];
__device__ __align__(16) float g_K     [93 * 48];
__device__ __align__(16) float g_stats1[2 * CDIM];
__device__ __align__(16) float g_scale1[CDIM];
__device__ __align__(16) float g_shift1[CDIM];
__device__ __align__(16) float g_stats2[2 * HDIM];
__device__ __align__(16) float g_scale2[HDIM];
__device__ __align__(16) float g_shift2[HDIM];
__device__ __align__(16) float g_pooled[GNUM * HDIM];
__device__ __align__(16) float g_counts[GNUM];
// CSR scratch
__device__ int g_cnt0  [NMAX];
__device__ int g_cnt1  [NMAX];
__device__ int g_base  [NMAX];
__device__ int g_cursor[NMAX];
__device__ int g_ei1   [EMAX];

// ---------------- helpers --------------------------------------------------
static __device__ __forceinline__ float softplusf_fast(float x) {
    return fmaxf(x, 0.f) + __logf(1.f + __expf(-fabsf(x)));
}
static __device__ __forceinline__ void red_add_v4(float* p, float a, float b, float c, float d) {
    asm volatile("red.global.add.v4.f32 [%0], {%1, %2, %3, %4};"
                 :: "l"(p), "f"(a), "f"(b), "f"(c), "f"(d) : "memory");
}
static __device__ __forceinline__ uint32_t f2tf32(float x) {
    uint32_t r;
    asm("cvt.rna.tf32.f32 %0, %1;" : "=r"(r) : "f"(x));
    return r;
}
static __device__ __forceinline__ void mma_tf32(float* d, const uint32_t* a, const uint32_t* b) {
    asm volatile(
        "mma.sync.aligned.m16n8k8.row.col.f32.tf32.tf32.f32 "
        "{%0,%1,%2,%3}, {%4,%5,%6,%7}, {%8,%9}, {%0,%1,%2,%3};"
        : "+f"(d[0]), "+f"(d[1]), "+f"(d[2]), "+f"(d[3])
        : "r"(a[0]), "r"(a[1]), "r"(a[2]), "r"(a[3]), "r"(b[0]), "r"(b[1]));
}

// message kernel inner math: sigmoid via FMA-Newton rcp, softplus via
// atanh-series log1p (FMA), exps stay on MUFU.  Accumulates den/num.
static __device__ __forceinline__ void msg_accum(
    float zf, float zc, float T, float& den, float& num)
{
    // sigmoid(zf) = r or ef*r, r = 1/(1+ef), ef = exp(-|zf|) in (0,1]
    float ef  = __expf(-fabsf(zf));
    float dfv = 1.f + ef;
    float rf  = fmaf(-0.5f, ef, 0.95711f);          // linear minimax init on [1,2]
    rf = rf * fmaf(-dfv, rf, 2.f);                  // Newton 1
    rf = rf * fmaf(-dfv, rf, 2.f);                  // Newton 2 (rel err ~1e-5)
    float sg = (zf >= 0.f) ? rf : ef * rf;

    // softplus(zc) = max(zc,0) + log(1+uc), uc = exp(-|zc|) in (0,1]
    // log(1+u) = 2*atanh(s), s = u/(2+u) in (0,1/3]
    float uc = __expf(-fabsf(zc));
    float dc = 2.f + uc;
    float rc = fmaf(-0.166666667f, dc, 0.82495f);   // init for 1/d on [2,3]
    rc = rc * fmaf(-dc, rc, 2.f);
    rc = rc * fmaf(-dc, rc, 2.f);
    float s  = uc * rc;
    float s2 = s * s;
    float p  = fmaf(fmaf(0.142857143f, s2, 0.2f), s2, 0.333333333f);
    p  = fmaf(p, s2, 1.f);
    float ln = (s + s) * p;                         // rel err ~2e-5
    float sp = fmaxf(zc, 0.f) + ln;

    float m  = sg * sp;
    float ew = __expf(T * m);
    den += ew;
    num = fmaf(m, ew, num);
}

// ---------------- tf32 tensor-core GEMM (3xTF32 accuracy) ------------------
__global__ void __launch_bounds__(256) tgemm(
    const float* __restrict__ A, const float* __restrict__ B,
    const float* __restrict__ bias,
    float* __restrict__ C0, int ldc0,
    float* __restrict__ C1, int ldc1, int splitN,
    int M, int N, int K, int lda, int ldb)
{
    __shared__ float sAhi[128][20], sAlo[128][20];
    __shared__ float sBhi[16][136], sBlo[16][136];

    const int tid   = threadIdx.x;
    const int lane  = tid & 31;
    const int wid   = tid >> 5;
    const int warpM = wid & 3;
    const int warpN = wid >> 2;
    const int g     = lane >> 2;
    const int t     = lane & 3;
    const int m0    = blockIdx.x * 128;
    const int n0    = blockIdx.y * 128;

    float cacc[2][8][4];
    #pragma unroll
    for (int mi = 0; mi < 2; mi++)
        #pragma unroll
        for (int nj = 0; nj < 8; nj++)
            #pragma unroll
            for (int q = 0; q < 4; q++) cacc[mi][nj][q] = 0.f;

    const int ar  = tid >> 1;
    const int akq = (tid & 1) * 8;
    const int bkr = tid >> 4;
    const int bnq = (tid & 15) * 8;

    for (int k0 = 0; k0 < K; k0 += 16) {
        {
            const int row = m0 + ar;
            const bool rok = row < M;
            #pragma unroll
            for (int i = 0; i < 8; i++) {
                const int kk = k0 + akq + i;
                float v = (rok && kk < K) ? A[(size_t)row * lda + kk] : 0.f;
                float hf = __uint_as_float(f2tf32(v));
                sAhi[ar][akq + i] = hf;
                sAlo[ar][akq + i] = __uint_as_float(f2tf32(v - hf));
            }
        }
        {
            const int kk = k0 + bkr;
            if (kk < K) {
                const float* bp = B + (size_t)kk * ldb + n0 + bnq;
                float4 v0 = *(const float4*)bp;
                float4 v1 = *(const float4*)(bp + 4);
                float vv[8] = {v0.x, v0.y, v0.z, v0.w, v1.x, v1.y, v1.z, v1.w};
                #pragma unroll
                for (int i = 0; i < 8; i++) {
                    float hf = __uint_as_float(f2tf32(vv[i]));
                    sBhi[bkr][bnq + i] = hf;
                    sBlo[bkr][bnq + i] = __uint_as_float(f2tf32(vv[i] - hf));
                }
            } else {
                #pragma unroll
                for (int i = 0; i < 8; i++) {
                    sBhi[bkr][bnq + i] = 0.f;
                    sBlo[bkr][bnq + i] = 0.f;
                }
            }
        }
        __syncthreads();

        #pragma unroll
        for (int ks = 0; ks < 16; ks += 8) {
            uint32_t ah[2][4], al[2][4];
            #pragma unroll
            for (int mi = 0; mi < 2; mi++) {
                const int r0 = warpM * 32 + mi * 16;
                ah[mi][0] = __float_as_uint(sAhi[r0 + g    ][ks + t    ]);
                ah[mi][1] = __float_as_uint(sAhi[r0 + g + 8][ks + t    ]);
                ah[mi][2] = __float_as_uint(sAhi[r0 + g    ][ks + t + 4]);
                ah[mi][3] = __float_as_uint(sAhi[r0 + g + 8][ks + t + 4]);
                al[mi][0] = __float_as_uint(sAlo[r0 + g    ][ks + t    ]);
                al[mi][1] = __float_as_uint(sAlo[r0 + g + 8][ks + t    ]);
                al[mi][2] = __float_as_uint(sAlo[r0 + g    ][ks + t + 4]);
                al[mi][3] = __float_as_uint(sAlo[r0 + g + 8][ks + t + 4]);
            }
            #pragma unroll
            for (int nj = 0; nj < 8; nj++) {
                const int cb = warpN * 64 + nj * 8 + g;
                uint32_t bh[2], bl[2];
                bh[0] = __float_as_uint(sBhi[ks + t    ][cb]);
                bh[1] = __float_as_uint(sBhi[ks + t + 4][cb]);
                bl[0] = __float_as_uint(sBlo[ks + t    ][cb]);
                bl[1] = __float_as_uint(sBlo[ks + t + 4][cb]);
                #pragma unroll
                for (int mi = 0; mi < 2; mi++) {
                    mma_tf32(cacc[mi][nj], ah[mi], bh);
                    mma_tf32(cacc[mi][nj], ah[mi], bl);
                    mma_tf32(cacc[mi][nj], al[mi], bh);
                }
            }
        }
        __syncthreads();
    }

    #pragma unroll
    for (int mi = 0; mi < 2; mi++) {
        #pragma unroll
        for (int half = 0; half < 2; half++) {
            const int row = m0 + warpM * 32 + mi * 16 + g + half * 8;
            if (row >= M) continue;
            #pragma unroll
            for (int nj = 0; nj < 8; nj++) {
                const int coln = n0 + warpN * 64 + nj * 8 + 2 * t;
                float2 v;
                v.x = cacc[mi][nj][half * 2 + 0] + bias[coln];
                v.y = cacc[mi][nj][half * 2 + 1] + bias[coln + 1];
                float* dst = (coln < splitN)
                           ? C0 + (size_t)row * ldc0 + coln
                           : C1 + (size_t)row * ldc1 + (coln - splitN);
                *(float2*)dst = v;
            }
        }
    }
}

// ---------------- zero scratch (replaces 7 memsets) ------------------------
__global__ void __launch_bounds__(256) zero_scratch(int N, int NHE)
{
    const int i = blockIdx.x * 256 + threadIdx.x;
    if (i < N)           g_cnt0[i] = 0;
    if (i < NHE)         g_cnt1[i] = 0;
    if (i < 512)         g_stats1[i] = 0.f;
    if (i < 256)         g_stats2[i] = 0.f;
    if (i < GNUM * HDIM) g_pooled[i] = 0.f;
    if (i < GNUM)        g_counts[i] = 0.f;
    if (i < 93 * 48)     g_K[i] = 0.f;
}

// ---------------- weight prep ----------------------------------------------
__global__ void __launch_bounds__(384) w1prep_fused(
    const float* __restrict__ embed_w, const float* __restrict__ embed_b,
    const float* __restrict__ lin_w)
{
    const int i = blockIdx.x;       // 0..92 (row 92 = bias)
    const int c = threadIdx.x;      // 0..383
    float acc;
    if (c < 256) {
        acc = 0.f;
        #pragma unroll 4
        for (int j = 0; j < 128; j++) {
            float we = (i < 92) ? embed_w[i * 128 + j] : embed_b[j];
            acc += we * (lin_w[j * 256 + c] + lin_w[(256 + j) * 256 + c]);
        }
    } else {
        acc = (i < 92) ? embed_w[i * 128 + (c - 256)] : embed_b[c - 256];
    }
    if (i < 92) g_W1f[i * 384 + c] = acc; else g_b1f[c] = acc;
}

__global__ void __launch_bounds__(256) w2prep(
    const float* __restrict__ bembed_w, const float* __restrict__ bembed_b,
    const float* __restrict__ lin_w, const float* __restrict__ lin_b)
{
    const int i = blockIdx.x;       // 0..40
    const int c = threadIdx.x;
    float acc = (i == 40) ? lin_b[c] : 0.f;
    #pragma unroll 4
    for (int j = 0; j < 128; j++) {
        float bw = (i < 40) ? bembed_w[i * 128 + j] : bembed_b[j];
        acc += bw * lin_w[(128 + j) * 256 + c];
    }
    if (i < 40) g_W2[i * 256 + c] = acc; else g_b2[c] = acc;
}

// ---------------- CSR build ------------------------------------------------
__global__ void __launch_bounds__(256) count_edges(
    const int* __restrict__ idx0, const int* __restrict__ idx1, int E)
{
    for (int e = blockIdx.x * 256 + threadIdx.x; e < E; e += gridDim.x * 256) {
        atomicAdd(&g_cnt0[idx0[e]], 1);
        atomicAdd(&g_cnt1[idx1[e]], 1);
    }
}

__global__ void __launch_bounds__(1024) scan_counts(int N)
{
    __shared__ int sh[1024];
    const int tid   = threadIdx.x;
    const int chunk = (N + 1023) / 1024;
    const int start = tid * chunk;
    const int end   = min(start + chunk, N);

    int s = 0;
    for (int i = start; i < end; i++) s += g_cnt0[i];
    sh[tid] = s;
    __syncthreads();
    for (int off = 1; off < 1024; off <<= 1) {
        int v = (tid >= off) ? sh[tid - off] : 0;
        __syncthreads();
        sh[tid] += v;
        __syncthreads();
    }
    int run = sh[tid] - s;
    for (int i = start; i < end; i++) {
        int c = g_cnt0[i];
        g_base[i]   = run;
        g_cursor[i] = run;
        run += c;
    }
}

__global__ void __launch_bounds__(256) scatter_edges(
    const int* __restrict__ idx0, const int* __restrict__ idx1, int E)
{
    for (int e = blockIdx.x * 256 + threadIdx.x; e < E; e += gridDim.x * 256) {
        int p = atomicAdd(&g_cursor[idx0[e]], 1);
        g_ei1[p] = idx1[e];
    }
}

// ---------------- S[n] = seg-sum of hedge rows over node n's edges ---------
__global__ void __launch_bounds__(256) shedge_gather(
    const float* __restrict__ hedge, int N)
{
    const int tid  = threadIdx.x;
    const int lane = tid & 31;
    const int n    = blockIdx.x * 8 + (tid >> 5);
    if (n >= N) return;

    const int base = g_base[n];
    const int cnt  = g_cnt0[n];
    float lo = 0.f, hi = 0.f;
    int k = 0;
    for (; k + 2 <= cnt; k += 2) {
        int m0 = g_ei1[base + k];
        int m1 = g_ei1[base + k + 1];
        const float* h0 = hedge + (size_t)m0 * 40;
        const float* h1 = hedge + (size_t)m1 * 40;
        lo += h0[lane] + h1[lane];
        if (lane < 8) hi += h0[32 + lane] + h1[32 + lane];
    }
    if (k < cnt) {
        const float* h0 = hedge + (size_t)g_ei1[base + k] * 40;
        lo += h0[lane];
        if (lane < 8) hi += h0[32 + lane];
    }
    g_S[(size_t)n * 48 + lane] = lo;
    if (lane < 8)  g_S[(size_t)n * 48 + 32 + lane] = hi;
    if (lane == 0) g_S[(size_t)n * 48 + 40] = (float)cnt;
}

// ---------------- K[93,41] = x^e^T @ S -------------------------------------
__global__ void __launch_bounds__(256) kgemm(const float* __restrict__ x, int N)
{
    __shared__ __align__(16) float sx[64][96];
    __shared__ __align__(16) float sS[64][48];
    const int tid = threadIdx.x;

    int task[4], ti[4], tj[4];
    float4 acc[4];
    #pragma unroll
    for (int t = 0; t < 4; t++) {
        task[t] = tid + t * 256;
        ti[t] = task[t] / 11;
        tj[t] = (task[t] % 11) * 4;
        acc[t] = make_float4(0.f, 0.f, 0.f, 0.f);
    }

    for (int n0 = blockIdx.x * 64; n0 < N; n0 += gridDim.x * 64) {
        for (int idx = tid; idx < 64 * 92; idx += 256) {
            int r = idx / 92, c = idx % 92;
            int n = n0 + r;
            sx[r][c] = (n < N) ? x[(size_t)n * 92 + c] : 0.f;
        }
        if (tid < 64) sx[tid][92] = (n0 + tid < N) ? 1.f : 0.f;
        for (int idx = tid; idx < 64 * 48; idx += 256) {
            int r = idx / 48, c = idx % 48;
            int n = n0 + r;
            sS[r][c] = (n < N) ? g_S[(size_t)n * 48 + c] : 0.f;
        }
        __syncthreads();

        for (int r = 0; r < 64; r++) {
            #pragma unroll
            for (int t = 0; t < 4; t++) {
                if (task[t] < 1023) {
                    float a = sx[r][ti[t]];
                    float4 v = *(const float4*)&sS[r][tj[t]];
                    acc[t].x += a * v.x; acc[t].y += a * v.y;
                    acc[t].z += a * v.z; acc[t].w += a * v.w;
                }
            }
        }
        __syncthreads();
    }

    #pragma unroll
    for (int t = 0; t < 4; t++) {
        if (task[t] < 1023) {
            float* kp = &g_K[ti[t] * 48 + tj[t]];
            atomicAdd(kp + 0, acc[t].x);
            atomicAdd(kp + 1, acc[t].y);
            atomicAdd(kp + 2, acc[t].z);
            atomicAdd(kp + 3, acc[t].w);
        }
    }
}

// ---------------- cross term: stats1[256+c] += 2 * W1e[:,c]^T K W2e[:,c] ---
__global__ void __launch_bounds__(256) cross_add()
{
    __shared__ float kr[48];
    const int i = blockIdx.x;      // 0..92
    const int c = threadIdx.x;
    if (c < 48) kr[c] = g_K[i * 48 + c];
    __syncthreads();

    float inner = g_b2[c] * kr[40];
    #pragma unroll 4
    for (int j = 0; j < 40; j++)
        inner += kr[j] * g_W2[j * 256 + c];
    float w1 = (i < 92) ? g_W1f[i * 384 + c] : g_b1f[c];
    atomicAdd(&g_stats1[256 + c], 2.f * w1 * inner);
}

// ---------------- degree-weighted self sums into BN1 stats -----------------
__global__ void __launch_bounds__(256) weighted_stats(
    const float* __restrict__ Z, const int* __restrict__ cnt, int R)
{
    __shared__ float ss[512];
    const int tid = threadIdx.x;
    for (int i = tid; i < 512; i += 256) ss[i] = 0.f;
    __syncthreads();

    const int gid = blockIdx.x * 256 + tid;
    const int r = gid >> 5;
    const int g = gid & 31;
    if (r < R) {
        const float w = (float)cnt[r];
        if (w > 0.f) {
            const float4* Z4 = (const float4*)Z;
            float4 z0 = Z4[(size_t)r * 64 + g];
            float4 z1 = Z4[(size_t)r * 64 + 32 + g];
            const int c = 4 * g;
            atomicAdd(&ss[c + 0], w * z0.x); atomicAdd(&ss[c + 1], w * z0.y);
            atomicAdd(&ss[c + 2], w * z0.z); atomicAdd(&ss[c + 3], w * z0.w);
            atomicAdd(&ss[128 + c + 0], w * z1.x); atomicAdd(&ss[128 + c + 1], w * z1.y);
            atomicAdd(&ss[128 + c + 2], w * z1.z); atomicAdd(&ss[128 + c + 3], w * z1.w);
            atomicAdd(&ss[256 + c + 0], w * z0.x * z0.x); atomicAdd(&ss[256 + c + 1], w * z0.y * z0.y);
            atomicAdd(&ss[256 + c + 2], w * z0.z * z0.z); atomicAdd(&ss[256 + c + 3], w * z0.w * z0.w);
            atomicAdd(&ss[384 + c + 0], w * z1.x * z1.x); atomicAdd(&ss[384 + c + 1], w * z1.y * z1.y);
            atomicAdd(&ss[384 + c + 2], w * z1.z * z1.z); atomicAdd(&ss[384 + c + 3], w * z1.w * z1.w);
        }
    }
    __syncthreads();
    for (int i = tid; i < 512; i += 256)
        if (ss[i] != 0.f) atomicAdd(&g_stats1[i], ss[i]);
}

// ---------------- BN finalize ----------------------------------------------
__global__ void bn_finalize(const float* __restrict__ stats,
                            const float* __restrict__ gma,
                            const float* __restrict__ bta,
                            float inv, int C,
                            float* __restrict__ scale, float* __restrict__ shift)
{
    const int c = blockIdx.x * blockDim.x + threadIdx.x;
    if (c < C) {
        float mean = stats[c] * inv;
        float var  = fmaxf(stats[C + c] * inv - mean * mean, 0.f);
        float s    = gma[c] * rsqrtf(var + 1e-5f);
        scale[c] = s;
        shift[c] = bta[c] - mean * s;
    }
}

// ---------------- message + softmax aggregation (warp per node, CSR) -------
__global__ void __launch_bounds__(256) node_aggregate(
    const float* __restrict__ aggr_t, int N)
{
    __shared__ float ss[256];
    const int tid = threadIdx.x;
    ss[tid] = 0.f;
    __syncthreads();

    const int lane = tid & 31;
    const int n = blockIdx.x * 8 + (tid >> 5);
    if (n < N) {
        const float4* zA4 = (const float4*)g_zA;
        const float4* zB4 = (const float4*)g_zB;
        const float4 sf = *(const float4*)&g_scale1[4 * lane];
        const float4 tf = *(const float4*)&g_shift1[4 * lane];
        const float4 sc = *(const float4*)&g_scale1[128 + 4 * lane];
        const float4 tc = *(const float4*)&g_shift1[128 + 4 * lane];
        const float  T  = *aggr_t;

        float4 a0 = zA4[(size_t)n * 64 + lane];
        float4 a1 = zA4[(size_t)n * 64 + 32 + lane];
        const float4 af = {a0.x * sf.x + tf.x, a0.y * sf.y + tf.y,
                           a0.z * sf.z + tf.z, a0.w * sf.w + tf.w};
        const float4 ac = {a1.x * sc.x + tc.x, a1.y * sc.y + tc.y,
                           a1.z * sc.z + tc.z, a1.w * sc.w + tc.w};

        const int base = g_base[n];
        const int cnt  = g_cnt0[n];

        float nx = 0, ny = 0, nz = 0, nw = 0;
        float dx = 0, dy = 0, dz = 0, dw = 0;

        #define PROC(mIdx)                                                    \
        {                                                                     \
            float4 b0 = zB4[(size_t)(mIdx) * 64 + lane];                      \
            float4 b1 = zB4[(size_t)(mIdx) * 64 + 32 + lane];                 \
            msg_accum(af.x + b0.x * sf.x, ac.x + b1.x * sc.x, T, dx, nx);     \
            msg_accum(af.y + b0.y * sf.y, ac.y + b1.y * sc.y, T, dy, ny);     \
            msg_accum(af.z + b0.z * sf.z, ac.z + b1.z * sc.z, T, dz, nz);     \
            msg_accum(af.w + b0.w * sf.w, ac.w + b1.w * sc.w, T, dw, nw);     \
        }

        int k = 0;
        for (; k + 2 <= cnt; k += 2) {
            int m0 = g_ei1[base + k];
            int m1 = g_ei1[base + k + 1];
            PROC(m0);
            PROC(m1);
        }
        if (k < cnt) {
            int m0 = g_ei1[base + k];
            PROC(m0);
        }
        #undef PROC

        float ox = nx / (dx + 1e-16f);
        float oy = ny / (dy + 1e-16f);
        float oz = nz / (dz + 1e-16f);
        float ow = nw / (dw + 1e-16f);

        ((float4*)g_out)[(size_t)n * 32 + lane] = make_float4(ox, oy, oz, ow);

        const int c = 4 * lane;
        atomicAdd(&ss[c + 0], ox); atomicAdd(&ss[c + 1], oy);
        atomicAdd(&ss[c + 2], oz); atomicAdd(&ss[c + 3], ow);
        atomicAdd(&ss[128 + c + 0], ox * ox); atomicAdd(&ss[128 + c + 1], oy * oy);
        atomicAdd(&ss[128 + c + 2], oz * oz); atomicAdd(&ss[128 + c + 3], ow * ow);
    }
    __syncthreads();
    if (ss[tid] != 0.f) atomicAdd(&g_stats2[tid], ss[tid]);
}

// ---------------- node final: h' = softplus(BN2(out)+h); pool + counts -----
__global__ void __launch_bounds__(256) node_final(
    const int* __restrict__ batch, int N)
{
    const int gid = blockIdx.x * 256 + threadIdx.x;
    const int n = gid >> 5;
    const int g = gid & 31;
    if (n >= N) return;

    float4 o  = ((const float4*)g_out)[(size_t)n * 32 + g];
    float4 s2 = *(const float4*)&g_scale2[4 * g];
    float4 t2 = *(const float4*)&g_shift2[4 * g];
    float4 hv = ((const float4*)g_h)[(size_t)n * 32 + g];

    float vx = softplusf_fast(o.x * s2.x + t2.x + hv.x);
    float vy = softplusf_fast(o.y * s2.y + t2.y + hv.y);
    float vz = softplusf_fast(o.z * s2.z + t2.z + hv.z);
    float vw = softplusf_fast(o.w * s2.w + t2.w + hv.w);

    const int b = batch[n];
    if (g == 0) atomicAdd(&g_counts[b], 1.f);
    red_add_v4(&g_pooled[(size_t)b * 128 + 4 * g], vx, vy, vz, vw);
}

// ---------------- head: mean pool -> softplus(MLP) -> linear ---------------
__global__ void __launch_bounds__(256) head(
    const float* __restrict__ l1_w, const float* __restrict__ l1_b,
    const float* __restrict__ out_w, const float* __restrict__ out_b,
    float* __restrict__ out)
{
    __shared__ float p[128];
    __shared__ float red[256];
    const int g = blockIdx.x;
    const int tid = threadIdx.x;
    if (tid < 128)
        p[tid] = g_pooled[g * 128 + tid] / fmaxf(g_counts[g], 1.f);
    __syncthreads();

    float acc = l1_b[tid];
    #pragma unroll 8
    for (int k = 0; k < 128; k++)
        acc += p[k] * l1_w[k * 256 + tid];
    red[tid] = softplusf_fast(acc) * out_w[tid];
    __syncthreads();
    for (int s = 128; s > 0; s >>= 1) {
        if (tid < s) red[tid] += red[tid + s];
        __syncthreads();
    }
    if (tid == 0) out[g] = red[0] + out_b[0];
}

// ---------------- launch ---------------------------------------------------
extern "C" void kernel_launch(void* const* d_in, const int* in_sizes, int n_in,
                              void* d_out, int out_size)
{
    const float* x        = (const float*)d_in[0];
    const float* hedge    = (const float*)d_in[1];
    const int*   rel      = (const int*)d_in[2];      // int32 (JAX x64 disabled)
    const int*   batch    = (const int*)d_in[3];      // int32
    const float* embed_w  = (const float*)d_in[5];
    const float* embed_b  = (const float*)d_in[6];
    const float* bembed_w = (const float*)d_in[7];
    const float* bembed_b = (const float*)d_in[8];
    const float* lin_w    = (const float*)d_in[9];
    const float* lin_b    = (const float*)d_in[10];
    const float* bn1_g    = (const float*)d_in[11];
    const float* bn1_b    = (const float*)d_in[12];
    const float* bn2_g    = (const float*)d_in[13];
    const float* bn2_b    = (const float*)d_in[14];
    const float* aggr_t   = (const float*)d_in[15];
    const float* l1_w     = (const float*)d_in[16];
    const float* l1_b     = (const float*)d_in[17];
    const float* out_w    = (const float*)d_in[18];
    const float* out_b    = (const float*)d_in[19];

    const int N   = in_sizes[0] / 92;
    const int NHE = in_sizes[1] / 40;
    const int E   = in_sizes[2] / 3;
    const int* idx0 = rel;
    const int* idx1 = rel + E;

    // side streams + events (created once; capture-legal)
    static cudaStream_t s2 = nullptr, s3 = nullptr;
    static cudaEvent_t evFork = nullptr, evCnt = nullptr, evJoin2 = nullptr, evJoin3 = nullptr;
    if (!s2) {
        cudaStreamCreateWithFlags(&s2, cudaStreamNonBlocking);
        cudaStreamCreateWithFlags(&s3, cudaStreamNonBlocking);
        cudaEventCreateWithFlags(&evFork,  cudaEventDisableTiming);
        cudaEventCreateWithFlags(&evCnt,   cudaEventDisableTiming);
        cudaEventCreateWithFlags(&evJoin2, cudaEventDisableTiming);
        cudaEventCreateWithFlags(&evJoin3, cudaEventDisableTiming);
    }

    void *p_h, *p_zA, *p_zB;
    void *p_st1, *p_sc1, *p_sh1, *p_st2, *p_sc2, *p_sh2;
    void *p_c0, *p_c1, *p_W1f, *p_b1f, *p_W2, *p_b2;
    cudaGetSymbolAddress(&p_h,   g_h);
    cudaGetSymbolAddress(&p_zA,  g_zA);
    cudaGetSymbolAddress(&p_zB,  g_zB);
    cudaGetSymbolAddress(&p_st1, g_stats1);
    cudaGetSymbolAddress(&p_sc1, g_scale1);
    cudaGetSymbolAddress(&p_sh1, g_shift1);
    cudaGetSymbolAddress(&p_st2, g_stats2);
    cudaGetSymbolAddress(&p_sc2, g_scale2);
    cudaGetSymbolAddress(&p_sh2, g_shift2);
    cudaGetSymbolAddress(&p_c0,  g_cnt0);
    cudaGetSymbolAddress(&p_c1,  g_cnt1);
    cudaGetSymbolAddress(&p_W1f, g_W1f);
    cudaGetSymbolAddress(&p_b1f, g_b1f);
    cudaGetSymbolAddress(&p_W2,  g_W2);
    cudaGetSymbolAddress(&p_b2,  g_b2);

    const dim3 t256(256);

    // single zero-fill kernel before the fork (replaces 7 memsets)
    zero_scratch<<<(NMAX + 255) / 256, t256>>>(N, NHE);

    cudaEventRecord(evFork, 0);
    cudaStreamWaitEvent(s2, evFork, 0);
    cudaStreamWaitEvent(s3, evFork, 0);

    // ---- s2: CSR + S + K chain (raw inputs only) ----
    count_edges  <<<1184, t256, 0, s2>>>(idx0, idx1, E);
    cudaEventRecord(evCnt, s2);                    // cnt0/cnt1 final here
    scan_counts  <<<1, 1024, 0, s2>>>(N);
    scatter_edges<<<1184, t256, 0, s2>>>(idx0, idx1, E);
    shedge_gather<<<(N + 7) / 8, t256, 0, s2>>>(hedge, N);
    kgemm        <<<232, t256, 0, s2>>>(x, N);
    cudaEventRecord(evJoin2, s2);

    // ---- s3: hedge-side weights + zB GEMM + zB stats ----
    w2prep<<<41, t256, 0, s3>>>(bembed_w, bembed_b, lin_w, lin_b);
    tgemm<<<dim3((NHE + 127) / 128, 2), t256, 0, s3>>>(
        hedge, (const float*)p_W2, (const float*)p_b2,
        (float*)p_zB, 256, (float*)p_zB, 256, 1 << 30,
        NHE, 256, 40, 40, 256);
    cudaStreamWaitEvent(s3, evCnt, 0);
    weighted_stats<<<(NHE * 32 + 255) / 256, t256, 0, s3>>>(
        (float*)p_zB, (const int*)p_c1, NHE);
    cudaEventRecord(evJoin3, s3);

    // ---- main: fused node-side GEMM + zA stats ----
    w1prep_fused<<<93, 384>>>(embed_w, embed_b, lin_w);
    tgemm<<<dim3((N + 127) / 128, 3), t256>>>(
        x, (const float*)p_W1f, (const float*)p_b1f,
        (float*)p_zA, 256, (float*)p_h, 128, 256,
        N, 384, 92, 92, 384);
    cudaStreamWaitEvent(0, evCnt, 0);
    weighted_stats<<<(N * 32 + 255) / 256, t256>>>(
        (float*)p_zA, (const int*)p_c0, N);

    // ---- join, cross term + BN1 finalize ----
    cudaStreamWaitEvent(0, evJoin2, 0);
    cudaStreamWaitEvent(0, evJoin3, 0);
    cross_add<<<93, t256>>>();
    bn_finalize<<<1, 256>>>((float*)p_st1, bn1_g, bn1_b, 1.0f / (float)E, 256,
                            (float*)p_sc1, (float*)p_sh1);

    // ---- message + softmax aggregation + BN2 ----
    node_aggregate<<<(N + 7) / 8, t256>>>(aggr_t, N);
    bn_finalize<<<1, 128>>>((float*)p_st2, bn2_g, bn2_b, 1.0f / (float)N, 128,
                            (float*)p_sc2, (float*)p_sh2);

    node_final<<<(N * 32 + 255) / 256, t256>>>(batch, N);
    head<<<GNUM, t256>>>(l1_w, l1_b, out_w, out_b, (float*)d_out);
}